// round 7
// baseline (speedup 1.0000x reference)
#include <cuda_runtime.h>
#include <cstdint>

// Problem constants
#define SQ 50
#define SP 3
#define SS 64
#define WORDS 192      // words per block
#define WPAIRS 96      // word pairs per block
#define THREADS 1024   // 32 warps; warp = 1 head duo; lane spans 3 word-pairs
#define TROWP 308      // floats per word-pair row (LDS.128 conflict-free walk)
#define COFF 200       // t2c offset within row (50 q * 2)

// Duplicated heads table: [q][duo(32)][12] = {h0,h0,h1,h1,h2,h2, h0',h0',h1',h1',h2',h2'}
#define HDUP_FLOATS (SQ * 384)   // 19200 floats = 76.8 KB

// smem float offsets
#define OFF_HR   HDUP_FLOATS           // 19200 (64)
#define OFF_PART (OFF_HR + SS)         // 19264 (32*192 = 6144)
#define OFF_RED  (OFF_PART + 32*WORDS) // 25408 (16 floats = 8 doubles)
#define OFF_R    (OFF_RED + 16)        // 25424 (96*308 floats; 16B aligned: 25424%4==0)
#define SMEM_FLOATS (OFF_R + WPAIRS * TROWP)   // 54992 floats = 219968 B

__device__ double       g_accum;
__device__ unsigned int g_count;
__device__ float        g_hdup[HDUP_FLOATS];
__device__ float        g_hr[SS];

__device__ __forceinline__ float softplus20(float x) {
    float y = x * 20.0f;
    return fmaxf(y, 0.0f) + log1pf(expf(-fabsf(y)));
}

// ---------------------------------------------------------------------------
__global__ void prep_kernel(const float* __restrict__ heads_param,
                            const float* __restrict__ hr_param) {
    const int tid = threadIdx.x;

    if (blockIdx.x == 0 && tid == 0) { g_accum = 0.0; g_count = 0u; }

    __shared__ float s_hr[SS];
    if (tid < SS) s_hr[tid] = softplus20(hr_param[tid]);
    __syncthreads();
    if (blockIdx.x == 0 && tid < SS) {
        float s = 0.0f;
        #pragma unroll
        for (int i = 0; i < SS; i++) s += s_hr[i];
        s = fmaxf(s, 1e-12f);
        g_hr[tid] = (s_hr[tid] / s + 0.001f / (float)SS) / 1.001f;
    }

    const int stride = blockDim.x * gridDim.x;
    for (int i = blockIdx.x * blockDim.x + tid; i < SS * SQ; i += stride) {
        int s = i / SQ;
        int q = i - s * SQ;
        const float* hp = heads_param + (s * SQ + q) * SP;
        float h0 = softplus20(hp[0]);
        float h1 = softplus20(hp[1]);
        float h2 = softplus20(hp[2]);
        float inv = 1.0f / fmaxf(h0 + h1 + h2, 1e-12f);
        h0 *= inv; h1 *= inv; h2 *= inv;
        int duo = s >> 1, o = s & 1;
        float* dst = g_hdup + q * 384 + duo * 12 + o * 6;
        dst[0] = h0; dst[1] = h0;
        dst[2] = h1; dst[3] = h1;
        dst[4] = h2; dst[5] = h2;
    }
}

// ---------------------------------------------------------------------------
// Main kernel.
// Row layout per word-pair wp (words A=2wp, B=2wp+1), TROWP floats:
//   [q*4 + 0..3] = after r-phase: {r0A, r0B, r1A, r1B}  (staged raw: {t0A,t0B,t1A,t1B})
//   [COFF + q*2 + 0..1] = {t2cA, t2cB}                  (staged raw: {t2A, t2B})
// dot = t2c * (h2 + h0*r0 + h1*r1); cov = p2 * sum_s hr_s * prod_q inner.
// ---------------------------------------------------------------------------
__global__ void __launch_bounds__(THREADS, 1)
main_kernel(const float* __restrict__ pauli,
            const float* __restrict__ coeff,
            float* __restrict__ out,
            int N, int nblocks) {
    extern __shared__ float smem[];
    float*  sh_h    = smem;
    float*  sh_hr   = smem + OFF_HR;
    float*  sh_part = smem + OFF_PART;
    double* sh_red  = (double*)(smem + OFF_RED);
    float*  sh_r    = smem + OFF_R;

    const int tid  = threadIdx.x;
    const int wid  = tid >> 5;      // duo id 0..31
    const int lane = tid & 31;

    // Stage duplicated heads
    {
        const float4* src = (const float4*)g_hdup;
        float4*       dst = (float4*)sh_h;
        #pragma unroll
        for (int i = tid; i < HDUP_FLOATS / 4; i += THREADS) dst[i] = src[i];
    }
    if (tid < SS) sh_hr[tid] = g_hr[tid];

    // Stage pauli tile: coalesced global reads, scatter into interleaved layout
    const int base  = blockIdx.x * WORDS;
    const int valid = min(WORDS, N - base);
    const int total = valid * (SQ * SP);
    const float* gsrc = pauli + (size_t)base * (SQ * SP);
    for (int f = tid; f < total; f += THREADS) {
        int w   = f / (SQ * SP);
        int rem = f - w * (SQ * SP);
        int q   = rem / SP;
        int p   = rem - q * SP;
        int wp  = w >> 1, o = w & 1;
        float val = gsrc[f];
        if (p < 2) sh_r[wp * TROWP + q * 4 + p * 2 + o] = val;
        else       sh_r[wp * TROWP + COFF + q * 2 + o]  = val;
    }
    __syncthreads();

    // r-phase: in-place convert raw t -> (r0, r1, t2c)
    for (int t = tid; t < WPAIRS * SQ; t += THREADS) {
        int wp = t & 127;                  // careful: 96 not pow2 -> use div
        wp = t % WPAIRS;
        int q  = t / WPAIRS;
        float* row = sh_r + wp * TROWP;
        float4 v  = *(float4*)(row + q * 4);        // t0A,t0B,t1A,t1B
        float2 c2 = *(float2*)(row + COFF + q * 2); // t2A, t2B
        float t2cA = fmaxf(c2.x, 1e-12f);
        float t2cB = fmaxf(c2.y, 1e-12f);
        float rcpA, rcpB;
        asm("rcp.approx.f32 %0, %1;" : "=f"(rcpA) : "f"(t2cA));
        asm("rcp.approx.f32 %0, %1;" : "=f"(rcpB) : "f"(t2cB));
        float4 rv;
        rv.x = v.x * rcpA; rv.y = v.y * rcpB;
        rv.z = v.z * rcpA; rv.w = v.w * rcpB;
        *(float4*)(row + q * 4) = rv;
        *(float2*)(row + COFF + q * 2) = make_float2(t2cA, t2cB);
    }
    __syncthreads();

    // Main loop: warp's duo = wid; lane covers wp in {lane, lane+32, lane+64}
    const ulonglong2* r0p = (const ulonglong2*)(sh_r + (lane     ) * TROWP);
    const ulonglong2* r1p = (const ulonglong2*)(sh_r + (lane + 32) * TROWP);
    const ulonglong2* r2p = (const ulonglong2*)(sh_r + (lane + 64) * TROWP);
    const char* hbase = (const char*)(sh_h + wid * 12);

    uint64_t a00, a01, a02, a10, a11, a12;
    a00 = a01 = a02 = a10 = a11 = a12 = 0x3F8000003F800000ull;

    #pragma unroll 2
    for (int q = 0; q < SQ; q++) {
        const ulonglong2* hq = (const ulonglong2*)(hbase + q * 1536);
        ulonglong2 A = hq[0];   // (H0, H1)   head s
        ulonglong2 B = hq[1];   // (H2, H0')  head s / s'
        ulonglong2 C = hq[2];   // (H1', H2') head s'
        ulonglong2 R0 = r0p[q * 2 + 0] , Rx;
        // NOTE: q*4 floats = 16B = 1 ulonglong2 -> index q
        R0 = ((const ulonglong2*)r0p)[q];
        ulonglong2 R1 = ((const ulonglong2*)r1p)[q];
        ulonglong2 R2 = ((const ulonglong2*)r2p)[q];
        (void)Rx;

        uint64_t d, e;
        asm("fma.rn.f32x2 %0, %1, %2, %3;" : "=l"(d) : "l"(A.x), "l"(R0.x), "l"(B.x));
        asm("fma.rn.f32x2 %0, %1, %2, %3;" : "=l"(d) : "l"(A.y), "l"(R0.y), "l"(d));
        asm("mul.rn.f32x2 %0, %1, %2;"     : "=l"(a00) : "l"(a00), "l"(d));
        asm("fma.rn.f32x2 %0, %1, %2, %3;" : "=l"(e) : "l"(B.y), "l"(R0.x), "l"(C.y));
        asm("fma.rn.f32x2 %0, %1, %2, %3;" : "=l"(e) : "l"(C.x), "l"(R0.y), "l"(e));
        asm("mul.rn.f32x2 %0, %1, %2;"     : "=l"(a10) : "l"(a10), "l"(e));

        asm("fma.rn.f32x2 %0, %1, %2, %3;" : "=l"(d) : "l"(A.x), "l"(R1.x), "l"(B.x));
        asm("fma.rn.f32x2 %0, %1, %2, %3;" : "=l"(d) : "l"(A.y), "l"(R1.y), "l"(d));
        asm("mul.rn.f32x2 %0, %1, %2;"     : "=l"(a01) : "l"(a01), "l"(d));
        asm("fma.rn.f32x2 %0, %1, %2, %3;" : "=l"(e) : "l"(B.y), "l"(R1.x), "l"(C.y));
        asm("fma.rn.f32x2 %0, %1, %2, %3;" : "=l"(e) : "l"(C.x), "l"(R1.y), "l"(e));
        asm("mul.rn.f32x2 %0, %1, %2;"     : "=l"(a11) : "l"(a11), "l"(e));

        asm("fma.rn.f32x2 %0, %1, %2, %3;" : "=l"(d) : "l"(A.x), "l"(R2.x), "l"(B.x));
        asm("fma.rn.f32x2 %0, %1, %2, %3;" : "=l"(d) : "l"(A.y), "l"(R2.y), "l"(d));
        asm("mul.rn.f32x2 %0, %1, %2;"     : "=l"(a02) : "l"(a02), "l"(d));
        asm("fma.rn.f32x2 %0, %1, %2, %3;" : "=l"(e) : "l"(B.y), "l"(R2.x), "l"(C.y));
        asm("fma.rn.f32x2 %0, %1, %2, %3;" : "=l"(e) : "l"(C.x), "l"(R2.y), "l"(e));
        asm("mul.rn.f32x2 %0, %1, %2;"     : "=l"(a12) : "l"(a12), "l"(e));
    }

    // hr-weighted duo sums -> partials[duo][word]
    {
        float hr0 = sh_hr[2 * wid], hr1 = sh_hr[2 * wid + 1];
        float lo0, hi0, lo1, hi1;
        float* pd = sh_part + wid * WORDS;

        asm("mov.b64 {%0, %1}, %2;" : "=f"(lo0), "=f"(hi0) : "l"(a00));
        asm("mov.b64 {%0, %1}, %2;" : "=f"(lo1), "=f"(hi1) : "l"(a10));
        *(float2*)(pd + 2 * lane) = make_float2(fmaf(hr0, lo0, hr1 * lo1),
                                                fmaf(hr0, hi0, hr1 * hi1));
        asm("mov.b64 {%0, %1}, %2;" : "=f"(lo0), "=f"(hi0) : "l"(a01));
        asm("mov.b64 {%0, %1}, %2;" : "=f"(lo1), "=f"(hi1) : "l"(a11));
        *(float2*)(pd + 2 * (lane + 32)) = make_float2(fmaf(hr0, lo0, hr1 * lo1),
                                                       fmaf(hr0, hi0, hr1 * hi1));
        asm("mov.b64 {%0, %1}, %2;" : "=f"(lo0), "=f"(hi0) : "l"(a02));
        asm("mov.b64 {%0, %1}, %2;" : "=f"(lo1), "=f"(hi1) : "l"(a12));
        *(float2*)(pd + 2 * (lane + 64)) = make_float2(fmaf(hr0, lo0, hr1 * lo1),
                                                       fmaf(hr0, hi0, hr1 * hi1));
    }
    __syncthreads();

    // Tail: thread w < 192 finishes word w
    double v = 0.0;
    if (tid < WORDS) {
        int n = base + tid;
        if (n < N) {
            float cov = 0.0f;
            #pragma unroll
            for (int d = 0; d < 32; d++) cov += sh_part[d * WORDS + tid];
            // p2 = prod of t2c over q (two fp32 halves)
            int wp = tid >> 1, o = tid & 1;
            const float* crow = sh_r + wp * TROWP + COFF + o;
            float p2a = 1.0f, p2b = 1.0f;
            #pragma unroll
            for (int q = 0; q < 25; q++) p2a *= crow[q * 2];
            #pragma unroll
            for (int q = 25; q < 50; q++) p2b *= crow[q * 2];
            float c = coeff[n];
            double cov_d = (double)cov * (double)p2a * (double)p2b;
            v = (double)(c * c) / cov_d;
        }
        #pragma unroll
        for (int off = 16; off; off >>= 1)
            v += __shfl_down_sync(0xFFFFFFFFu, v, off);
        if ((tid & 31) == 0) sh_red[tid >> 5] = v;
    }
    __syncthreads();
    if (tid == 0) {
        double s = 0.0;
        #pragma unroll
        for (int w = 0; w < 6; w++) s += sh_red[w];
        atomicAdd(&g_accum, s);
        __threadfence();
        unsigned int ticket = atomicAdd(&g_count, 1u);
        if (ticket == (unsigned int)(nblocks - 1)) {
            out[0] = (float)g_accum;
        }
    }
}

// ---------------------------------------------------------------------------
extern "C" void kernel_launch(void* const* d_in, const int* in_sizes, int n_in,
                              void* d_out, int out_size) {
    const float* pauli = (const float*)d_in[0];   // [N, 50, 3] f32
    const float* coeff = (const float*)d_in[1];   // [N] f32
    const float* heads = (const float*)d_in[2];   // [64, 50, 3] f32
    const float* hr    = (const float*)d_in[3];   // [64] f32
    const int N = in_sizes[1];

    const size_t smem = (size_t)SMEM_FLOATS * sizeof(float);   // 219968 B
    cudaFuncSetAttribute(main_kernel, cudaFuncAttributeMaxDynamicSharedMemorySize, (int)smem);

    prep_kernel<<<25, 128>>>(heads, hr);
    const int grid = (N + WORDS - 1) / WORDS;
    main_kernel<<<grid, THREADS, smem>>>(pauli, coeff, (float*)d_out, N, grid);
}

// round 8
// speedup vs baseline: 1.1180x; 1.1180x over previous
#include <cuda_runtime.h>
#include <cstdint>

// Problem constants
#define SQ 50
#define SP 3
#define SS 64
#define WORDS 256      // words per block
#define WPAIRS 128     // word pairs per block
#define THREADS 512    // 16 warps
#define NGROUPS 8      // word-pair groups (2 warps each: heads 0-31 / 32-63)
#define M 16           // word-pairs per group
#define TROWP 308      // floats per word-pair row (308 mod 32 = 20 -> conflict-free)
#define COFF 200       // t2c offset within row

// heads table: [q][head][4] = {h0, h1, h2, 0}
#define H4_FLOATS (SQ * SS * 4)        // 12800 floats

// smem float offsets
#define OFF_HR   H4_FLOATS             // 12800 (64)
#define OFF_PART (OFF_HR + SS)         // 12864 (2*128 float2 = 512 floats; 8B aligned)
#define OFF_RED  (OFF_PART + 512)      // 13376 (16 floats = 8 doubles)
#define OFF_R    (OFF_RED + 16)        // 13392 (16B aligned: 13392*4 % 16 == 0)
#define SMEM_FLOATS (OFF_R + WPAIRS * TROWP)   // 52816 floats = 211264 B

__device__ double       g_accum;
__device__ unsigned int g_count;
__device__ float        g_h4[H4_FLOATS];
__device__ float        g_hr[SS];

__device__ __forceinline__ float softplus20(float x) {
    float y = x * 20.0f;
    return fmaxf(y, 0.0f) + log1pf(expf(-fabsf(y)));
}

// ---------------------------------------------------------------------------
__global__ void prep_kernel(const float* __restrict__ heads_param,
                            const float* __restrict__ hr_param) {
    const int tid = threadIdx.x;

    if (blockIdx.x == 0 && tid == 0) { g_accum = 0.0; g_count = 0u; }

    __shared__ float s_hr[SS];
    if (tid < SS) s_hr[tid] = softplus20(hr_param[tid]);
    __syncthreads();
    if (blockIdx.x == 0 && tid < SS) {
        float s = 0.0f;
        #pragma unroll
        for (int i = 0; i < SS; i++) s += s_hr[i];
        s = fmaxf(s, 1e-12f);
        g_hr[tid] = (s_hr[tid] / s + 0.001f / (float)SS) / 1.001f;
    }

    const int stride = blockDim.x * gridDim.x;
    for (int i = blockIdx.x * blockDim.x + tid; i < SS * SQ; i += stride) {
        int s = i / SQ;
        int q = i - s * SQ;
        const float* hp = heads_param + (s * SQ + q) * SP;
        float h0 = softplus20(hp[0]);
        float h1 = softplus20(hp[1]);
        float h2 = softplus20(hp[2]);
        float inv = 1.0f / fmaxf(h0 + h1 + h2, 1e-12f);
        float* dst = g_h4 + (q * SS + s) * 4;
        dst[0] = h0 * inv;
        dst[1] = h1 * inv;
        dst[2] = h2 * inv;
        dst[3] = 0.0f;
    }
}

// ---------------------------------------------------------------------------
// Main kernel. Row per word-pair wp (words A=2wp, B=2wp+1):
//   [q*4 .. q*4+3]      after r-phase: {r0A, r0B, r1A, r1B}
//   [COFF + q*2 ..]     {t2cA, t2cB}
// dot = t2c * (h2 + h0*r0 + h1*r1); cov = p2 * sum_s hr_s * prod_q inner.
// Warp 2g+hh: heads hh*32+lane, word-pairs [g*M, (g+1)*M).
// ---------------------------------------------------------------------------
__global__ void __launch_bounds__(THREADS, 1)
main_kernel(const float* __restrict__ pauli,
            const float* __restrict__ coeff,
            float* __restrict__ out,
            int N, int nblocks) {
    extern __shared__ float smem[];
    float*  sh_h    = smem;
    float*  sh_hr   = smem + OFF_HR;
    float2* sh_part = (float2*)(smem + OFF_PART);
    double* sh_red  = (double*)(smem + OFF_RED);
    float*  sh_r    = smem + OFF_R;

    const int tid  = threadIdx.x;
    const int wid  = tid >> 5;
    const int lane = tid & 31;

    // Stage heads table
    {
        const float4* src = (const float4*)g_h4;
        float4*       dst = (float4*)sh_h;
        #pragma unroll
        for (int i = tid; i < H4_FLOATS / 4; i += THREADS) dst[i] = src[i];
    }
    if (tid < SS) sh_hr[tid] = g_hr[tid];

    // Stage pauli tile: coalesced reads, scatter to interleaved word-pair rows
    const int base  = blockIdx.x * WORDS;
    const int valid = min(WORDS, N - base);
    const int total = valid * (SQ * SP);
    const float* gsrc = pauli + (size_t)base * (SQ * SP);
    for (int f = tid; f < total; f += THREADS) {
        int w   = f / (SQ * SP);
        int rem = f - w * (SQ * SP);
        int q   = rem / SP;
        int p   = rem - q * SP;
        int wp  = w >> 1, o = w & 1;
        float val = gsrc[f];
        if (p < 2) sh_r[wp * TROWP + q * 4 + p * 2 + o] = val;
        else       sh_r[wp * TROWP + COFF + q * 2 + o]  = val;
    }
    __syncthreads();

    // r-phase: in-place raw t -> (r0A, r0B, r1A, r1B) + clamped t2c
    for (int t = tid; t < WPAIRS * SQ; t += THREADS) {
        int wp = t & (WPAIRS - 1);
        int q  = t >> 7;
        float* row = sh_r + wp * TROWP;
        float4 v  = *(float4*)(row + q * 4);        // t0A,t0B,t1A,t1B
        float2 c2 = *(float2*)(row + COFF + q * 2); // t2A,t2B
        float t2cA = fmaxf(c2.x, 1e-12f);
        float t2cB = fmaxf(c2.y, 1e-12f);
        float rcpA, rcpB;
        asm("rcp.approx.f32 %0, %1;" : "=f"(rcpA) : "f"(t2cA));
        asm("rcp.approx.f32 %0, %1;" : "=f"(rcpB) : "f"(t2cB));
        float4 rv;
        rv.x = v.x * rcpA; rv.y = v.y * rcpB;
        rv.z = v.z * rcpA; rv.w = v.w * rcpB;
        *(float4*)(row + q * 4) = rv;
        *(float2*)(row + COFF + q * 2) = make_float2(t2cA, t2cB);
    }
    __syncthreads();

    // Main loop
    const int g    = wid >> 1;
    const int hh   = wid & 1;
    const int head = hh * 32 + lane;
    const float4* hvec = (const float4*)sh_h;                 // [q*64 + head]
    const char*   rb   = (const char*)(sh_r + g * M * TROWP); // + m*1232 + q*16

    uint64_t acc[M];
    #pragma unroll
    for (int m = 0; m < M; m++) acc[m] = 0x3F8000003F800000ull;

    #pragma unroll 1
    for (int q = 0; q < SQ; q++) {
        float4 h4 = hvec[q * SS + head];
        uint64_t H0, H1, H2;
        asm("mov.b64 %0, {%1, %1};" : "=l"(H0) : "f"(h4.x));
        asm("mov.b64 %0, {%1, %1};" : "=l"(H1) : "f"(h4.y));
        asm("mov.b64 %0, {%1, %1};" : "=l"(H2) : "f"(h4.z));
        #pragma unroll
        for (int m = 0; m < M; m++) {
            ulonglong2 R = *(const ulonglong2*)(rb + m * (TROWP * 4) + q * 16);
            uint64_t d;
            asm("fma.rn.f32x2 %0, %1, %2, %3;" : "=l"(d) : "l"(H0), "l"(R.x), "l"(H2));
            asm("fma.rn.f32x2 %0, %1, %2, %3;" : "=l"(d) : "l"(H1), "l"(R.y), "l"(d));
            asm("mul.rn.f32x2 %0, %1, %2;"     : "=l"(acc[m]) : "l"(acc[m]), "l"(d));
        }
    }

    // Scale by hr[head], then butterfly-sum over the warp's 32 heads (f32x2)
    {
        float hrv = sh_hr[head];
        uint64_t HR;
        asm("mov.b64 %0, {%1, %1};" : "=l"(HR) : "f"(hrv));
        #pragma unroll
        for (int m = 0; m < M; m++)
            asm("mul.rn.f32x2 %0, %1, %2;" : "=l"(acc[m]) : "l"(acc[m]), "l"(HR));
        #pragma unroll
        for (int off = 16; off; off >>= 1) {
            #pragma unroll
            for (int m = 0; m < M; m++) {
                uint64_t o64 = __shfl_xor_sync(0xFFFFFFFFu,
                                               (unsigned long long)acc[m], off);
                asm("add.rn.f32x2 %0, %1, %2;" : "=l"(acc[m]) : "l"(acc[m]), "l"(o64));
            }
        }
        if (lane == 0) {
            float2* pd = sh_part + hh * WPAIRS + g * M;
            #pragma unroll
            for (int m = 0; m < M; m++) {
                float lo, hi;
                asm("mov.b64 {%0, %1}, %2;" : "=f"(lo), "=f"(hi) : "l"(acc[m]));
                pd[m] = make_float2(lo, hi);
            }
        }
    }
    __syncthreads();

    // Tail: thread w < 256 finishes word w
    double v = 0.0;
    if (tid < WORDS) {
        int n = base + tid;
        if (n < N) {
            int wp = tid >> 1, o = tid & 1;
            float2 pa = sh_part[wp];
            float2 pb = sh_part[WPAIRS + wp];
            float cov = o ? (pa.y + pb.y) : (pa.x + pb.x);
            const float* crow = sh_r + wp * TROWP + COFF + o;
            float p2a = 1.0f, p2b = 1.0f;
            #pragma unroll
            for (int q = 0; q < 25; q++) p2a *= crow[q * 2];
            #pragma unroll
            for (int q = 25; q < 50; q++) p2b *= crow[q * 2];
            float c = coeff[n];
            double covd = (double)cov * (double)p2a * (double)p2b;
            v = (double)(c * c) / covd;
        }
        #pragma unroll
        for (int off = 16; off; off >>= 1)
            v += __shfl_down_sync(0xFFFFFFFFu, v, off);
        if ((tid & 31) == 0) sh_red[tid >> 5] = v;
    }
    __syncthreads();
    if (tid == 0) {
        double s = 0.0;
        #pragma unroll
        for (int w = 0; w < WORDS / 32; w++) s += sh_red[w];
        atomicAdd(&g_accum, s);
        __threadfence();
        unsigned int ticket = atomicAdd(&g_count, 1u);
        if (ticket == (unsigned int)(nblocks - 1)) {
            out[0] = (float)g_accum;
        }
    }
}

// ---------------------------------------------------------------------------
extern "C" void kernel_launch(void* const* d_in, const int* in_sizes, int n_in,
                              void* d_out, int out_size) {
    const float* pauli = (const float*)d_in[0];   // [N, 50, 3] f32
    const float* coeff = (const float*)d_in[1];   // [N] f32
    const float* heads = (const float*)d_in[2];   // [64, 50, 3] f32
    const float* hr    = (const float*)d_in[3];   // [64] f32
    const int N = in_sizes[1];

    const size_t smem = (size_t)SMEM_FLOATS * sizeof(float);   // 211264 B
    cudaFuncSetAttribute(main_kernel, cudaFuncAttributeMaxDynamicSharedMemorySize, (int)smem);

    prep_kernel<<<25, 128>>>(heads, hr);
    const int grid = (N + WORDS - 1) / WORDS;
    main_kernel<<<grid, THREADS, smem>>>(pauli, coeff, (float*)d_out, N, grid);
}

// round 9
// speedup vs baseline: 1.1542x; 1.0324x over previous
#include <cuda_runtime.h>
#include <cstdint>

// Problem constants
#define SQ 50
#define SP 3
#define SS 64
#define WORDS 256      // words per block
#define THREADS 512    // 16 warps; warp quads split 64 heads, 2 words/thread
#define TROWS 80       // floats per word per slab (320B row; 20x16B -> conflict-free)

// Slabs: slab0 = q[0,26) (78 floats, 39 x 8B chunks); slab1 = q[26,50) (72 floats, 36 chunks)
#define Q0N 26
#define CH0 39
#define CH1 36

// Packed heads: ha[q][j(32)][4] = {h0s0,h0s1,h1s0,h1s1}
//               hcp[q][jp(16)][4] = {h2(2jp)s0, h2(2jp)s1, h2(2jp+1)s0, h2(2jp+1)s1}
#define HA_TOTAL (SQ * 128)   // 6400
#define HCP_TOTAL (SQ * 64)   // 3200

// smem float offsets
#define OFF_HCP  HA_TOTAL              // 6400
#define OFF_HR   (OFF_HCP + HCP_TOTAL) // 9600
#define OFF_PART (OFF_HR + SS)         // 9664 (3*256)
#define OFF_RED  (OFF_PART + 3*WORDS)  // 10432 (16 floats = 8 doubles)
#define OFF_TS0  (OFF_RED + 16)        // 10448 (x4 = 41792, 16B aligned)
#define OFF_TS1  (OFF_TS0 + WORDS*TROWS)  // 30928
#define SMEM_FLOATS (OFF_TS1 + WORDS*TROWS)  // 51408 floats = 205632 B

__device__ double       g_accum;
__device__ unsigned int g_count;
__device__ float        g_ha[HA_TOTAL];
__device__ float        g_hcp[HCP_TOTAL];
__device__ float        g_hr[SS];

__device__ __forceinline__ float softplus20(float x) {
    float y = x * 20.0f;
    return fmaxf(y, 0.0f) + log1pf(expf(-fabsf(y)));
}

// ---------------------------------------------------------------------------
__global__ void prep_kernel(const float* __restrict__ heads_param,
                            const float* __restrict__ hr_param) {
    const int tid = threadIdx.x;

    if (blockIdx.x == 0 && tid == 0) { g_accum = 0.0; g_count = 0u; }

    __shared__ float s_hr[SS];
    if (tid < SS) s_hr[tid] = softplus20(hr_param[tid]);
    __syncthreads();
    if (blockIdx.x == 0 && tid < SS) {
        float s = 0.0f;
        #pragma unroll
        for (int i = 0; i < SS; i++) s += s_hr[i];
        s = fmaxf(s, 1e-12f);
        g_hr[tid] = (s_hr[tid] / s + 0.001f / (float)SS) / 1.001f;
    }

    const int stride = blockDim.x * gridDim.x;
    for (int i = blockIdx.x * blockDim.x + tid; i < SS * SQ; i += stride) {
        int s = i / SQ;
        int q = i - s * SQ;
        const float* hp = heads_param + (s * SQ + q) * SP;
        float h0 = softplus20(hp[0]);
        float h1 = softplus20(hp[1]);
        float h2 = softplus20(hp[2]);
        float inv = 1.0f / fmaxf(h0 + h1 + h2, 1e-12f);
        h0 *= inv; h1 *= inv; h2 *= inv;
        int j = s >> 1, o = s & 1;
        int jp = j >> 1, jo = j & 1;
        g_ha[q * 128 + j * 4 + 0 + o]        = h0;
        g_ha[q * 128 + j * 4 + 2 + o]        = h1;
        g_hcp[q * 64 + jp * 4 + jo * 2 + o]  = h2;
    }
}

// ---------------------------------------------------------------------------
// Per-q step: 2 words x 8 head-pairs. dot = t2c*(h2 + h0*(t0/t2c) + h1*(t1/t2c))
// ---------------------------------------------------------------------------
__device__ __forceinline__ void proc_q2(
    bool first_half,
    float t0a, float t1a, float t2a,
    float t0b, float t1b, float t2b,
    const ulonglong2* __restrict__ ha,   // q-row, quarter-offset (8 entries)
    const ulonglong2* __restrict__ hcp,  // q-row, quarter-offset (4 entries)
    uint64_t* __restrict__ accA, uint64_t* __restrict__ accB,
    float& pAa, float& pAb, float& pBa, float& pBb)
{
    float t2ca = fmaxf(t2a, 1e-12f);
    float t2cb = fmaxf(t2b, 1e-12f);
    float ra, rb;
    asm("rcp.approx.f32 %0, %1;" : "=f"(ra) : "f"(t2ca));
    asm("rcp.approx.f32 %0, %1;" : "=f"(rb) : "f"(t2cb));
    float r0a = t0a * ra, r1a = t1a * ra;
    float r0b = t0b * rb, r1b = t1b * rb;
    if (first_half) { pAa *= t2ca; pBa *= t2cb; }
    else            { pAb *= t2ca; pBb *= t2cb; }

    uint64_t R0A, R1A, R0B, R1B;
    asm("mov.b64 %0, {%1, %1};" : "=l"(R0A) : "f"(r0a));
    asm("mov.b64 %0, {%1, %1};" : "=l"(R1A) : "f"(r1a));
    asm("mov.b64 %0, {%1, %1};" : "=l"(R0B) : "f"(r0b));
    asm("mov.b64 %0, {%1, %1};" : "=l"(R1B) : "f"(r1b));

    #pragma unroll
    for (int jp = 0; jp < 4; jp++) {
        ulonglong2 HcP = hcp[jp];
        ulonglong2 Ha0 = ha[2 * jp];
        ulonglong2 Ha1 = ha[2 * jp + 1];
        uint64_t dA, dB;
        // j = 2jp
        asm("fma.rn.f32x2 %0, %1, %2, %3;" : "=l"(dA) : "l"(Ha0.x), "l"(R0A), "l"(HcP.x));
        asm("fma.rn.f32x2 %0, %1, %2, %3;" : "=l"(dB) : "l"(Ha0.x), "l"(R0B), "l"(HcP.x));
        asm("fma.rn.f32x2 %0, %1, %2, %3;" : "=l"(dA) : "l"(Ha0.y), "l"(R1A), "l"(dA));
        asm("fma.rn.f32x2 %0, %1, %2, %3;" : "=l"(dB) : "l"(Ha0.y), "l"(R1B), "l"(dB));
        asm("mul.rn.f32x2 %0, %1, %2;" : "=l"(accA[2*jp]) : "l"(accA[2*jp]), "l"(dA));
        asm("mul.rn.f32x2 %0, %1, %2;" : "=l"(accB[2*jp]) : "l"(accB[2*jp]), "l"(dB));
        // j = 2jp+1
        asm("fma.rn.f32x2 %0, %1, %2, %3;" : "=l"(dA) : "l"(Ha1.x), "l"(R0A), "l"(HcP.y));
        asm("fma.rn.f32x2 %0, %1, %2, %3;" : "=l"(dB) : "l"(Ha1.x), "l"(R0B), "l"(HcP.y));
        asm("fma.rn.f32x2 %0, %1, %2, %3;" : "=l"(dA) : "l"(Ha1.y), "l"(R1A), "l"(dA));
        asm("fma.rn.f32x2 %0, %1, %2, %3;" : "=l"(dB) : "l"(Ha1.y), "l"(R1B), "l"(dB));
        asm("mul.rn.f32x2 %0, %1, %2;" : "=l"(accA[2*jp+1]) : "l"(accA[2*jp+1]), "l"(dA));
        asm("mul.rn.f32x2 %0, %1, %2;" : "=l"(accB[2*jp+1]) : "l"(accB[2*jp+1]), "l"(dB));
    }
}

// ---------------------------------------------------------------------------
__global__ void __launch_bounds__(THREADS, 1)
main_kernel(const float* __restrict__ pauli,
            const float* __restrict__ coeff,
            float* __restrict__ out,
            int N, int nblocks) {
    extern __shared__ float smem[];
    float*  sh_ha   = smem;
    float*  sh_hcp  = smem + OFF_HCP;
    float*  sh_hr   = smem + OFF_HR;
    float*  sh_part = smem + OFF_PART;
    double* sh_red  = (double*)(smem + OFF_RED);
    float*  sh_ts0  = smem + OFF_TS0;
    float*  sh_ts1  = smem + OFF_TS1;

    const int tid  = threadIdx.x;
    const int wid  = tid >> 5;
    const int lane = tid & 31;

    const int base  = blockIdx.x * WORDS;
    const int valid = min(WORDS, N - base);
    const float* gsrc = pauli + (size_t)base * (SQ * SP);

    const unsigned ts0_addr = (unsigned)__cvta_generic_to_shared(sh_ts0);
    const unsigned ts1_addr = (unsigned)__cvta_generic_to_shared(sh_ts1);

    // Issue slab0 cp.async (group 0)
    for (int i = tid; i < valid * CH0; i += THREADS) {
        int w = i / CH0, k = i - w * CH0;
        unsigned dst = ts0_addr + (unsigned)(w * TROWS + 2 * k) * 4u;
        const float* src = gsrc + w * 150 + 2 * k;
        asm volatile("cp.async.ca.shared.global [%0], [%1], 8;" :: "r"(dst), "l"(src));
    }
    asm volatile("cp.async.commit_group;" ::: "memory");

    // Issue slab1 cp.async (group 1)
    for (int i = tid; i < valid * CH1; i += THREADS) {
        int w = i / CH1, k = i - w * CH1;
        unsigned dst = ts1_addr + (unsigned)(w * TROWS + 2 * k) * 4u;
        const float* src = gsrc + w * 150 + Q0N * 3 + 2 * k;
        asm volatile("cp.async.ca.shared.global [%0], [%1], 8;" :: "r"(dst), "l"(src));
    }
    asm volatile("cp.async.commit_group;" ::: "memory");

    // Stage heads tables while cp.async is in flight
    {
        const float4* src = (const float4*)g_ha;
        float4*       dst = (float4*)sh_ha;
        #pragma unroll
        for (int i = tid; i < HA_TOTAL / 4; i += THREADS) dst[i] = src[i];
        const float4* src2 = (const float4*)g_hcp;
        float4*       dst2 = (float4*)sh_hcp;
        #pragma unroll
        for (int i = tid; i < HCP_TOTAL / 4; i += THREADS) dst2[i] = src2[i];
    }
    if (tid < SS) sh_hr[tid] = g_hr[tid];

    const int quarter = wid & 3;
    const int group   = wid >> 2;
    const int wA = group * 64 + lane;
    const int wB = wA + 32;

    uint64_t accA[8], accB[8];
    #pragma unroll
    for (int j = 0; j < 8; j++) { accA[j] = 0x3F8000003F800000ull; accB[j] = accA[j]; }
    float pAa = 1.0f, pAb = 1.0f, pBa = 1.0f, pBb = 1.0f;

    // ---- slab0: q 0..25 ----
    asm volatile("cp.async.wait_group 1;" ::: "memory");
    __syncthreads();
    {
        const float4* tvA = (const float4*)(sh_ts0 + wA * TROWS);
        const float4* tvB = (const float4*)(sh_ts0 + wB * TROWS);
        #pragma unroll 2
        for (int c = 0; c < 6; c++) {
            float4 A0 = tvA[3*c+0], A1 = tvA[3*c+1], A2 = tvA[3*c+2];
            float4 B0 = tvB[3*c+0], B1 = tvB[3*c+1], B2 = tvB[3*c+2];
            int q = 4 * c;
            const ulonglong2* ha  = (const ulonglong2*)(sh_ha  + q * 128);
            const ulonglong2* hcp = (const ulonglong2*)(sh_hcp + q * 64);
            const ulonglong2* haQ0  = ha  + quarter * 8;
            const ulonglong2* hcpQ0 = hcp + quarter * 4;
            proc_q2(true, A0.x, A0.y, A0.z, B0.x, B0.y, B0.z, haQ0,      hcpQ0,      accA, accB, pAa, pAb, pBa, pBb);
            proc_q2(true, A0.w, A1.x, A1.y, B0.w, B1.x, B1.y, haQ0 + 32, hcpQ0 + 16, accA, accB, pAa, pAb, pBa, pBb);
            proc_q2(true, A1.z, A1.w, A2.x, B1.z, B1.w, B2.x, haQ0 + 64, hcpQ0 + 32, accA, accB, pAa, pAb, pBa, pBb);
            proc_q2(true, A2.y, A2.z, A2.w, B2.y, B2.z, B2.w, haQ0 + 96, hcpQ0 + 48, accA, accB, pAa, pAb, pBa, pBb);
        }
        {   // q = 24, 25 (floats 72..77)
            const float2* a2 = (const float2*)(sh_ts0 + wA * TROWS + 72);
            const float2* b2 = (const float2*)(sh_ts0 + wB * TROWS + 72);
            float2 ua = a2[0], va = a2[1], wa2 = a2[2];
            float2 ub = b2[0], vb = b2[1], wb2 = b2[2];
            const ulonglong2* ha24  = (const ulonglong2*)(sh_ha  + 24 * 128) + quarter * 8;
            const ulonglong2* hcp24 = (const ulonglong2*)(sh_hcp + 24 * 64) + quarter * 4;
            proc_q2(true,  ua.x, ua.y, va.x, ub.x, ub.y, vb.x, ha24,      hcp24,      accA, accB, pAa, pAb, pBa, pBb);
            proc_q2(false, va.y, wa2.x, wa2.y, vb.y, wb2.x, wb2.y, ha24 + 32, hcp24 + 16, accA, accB, pAa, pAb, pBa, pBb);
        }
    }

    // ---- slab1: q 26..49 ----
    asm volatile("cp.async.wait_group 0;" ::: "memory");
    __syncthreads();
    {
        const float4* tvA = (const float4*)(sh_ts1 + wA * TROWS);
        const float4* tvB = (const float4*)(sh_ts1 + wB * TROWS);
        #pragma unroll 2
        for (int c = 0; c < 6; c++) {
            float4 A0 = tvA[3*c+0], A1 = tvA[3*c+1], A2 = tvA[3*c+2];
            float4 B0 = tvB[3*c+0], B1 = tvB[3*c+1], B2 = tvB[3*c+2];
            int q = Q0N + 4 * c;
            const ulonglong2* haQ0  = (const ulonglong2*)(sh_ha  + q * 128) + quarter * 8;
            const ulonglong2* hcpQ0 = (const ulonglong2*)(sh_hcp + q * 64) + quarter * 4;
            proc_q2(false, A0.x, A0.y, A0.z, B0.x, B0.y, B0.z, haQ0,      hcpQ0,      accA, accB, pAa, pAb, pBa, pBb);
            proc_q2(false, A0.w, A1.x, A1.y, B0.w, B1.x, B1.y, haQ0 + 32, hcpQ0 + 16, accA, accB, pAa, pAb, pBa, pBb);
            proc_q2(false, A1.z, A1.w, A2.x, B1.z, B1.w, B2.x, haQ0 + 64, hcpQ0 + 32, accA, accB, pAa, pAb, pBa, pBb);
            proc_q2(false, A2.y, A2.z, A2.w, B2.y, B2.z, B2.w, haQ0 + 96, hcpQ0 + 48, accA, accB, pAa, pAb, pBa, pBb);
        }
    }

    // hr-weighted sums over this quarter's 16 heads
    float partA = 0.0f, partB = 0.0f;
    const float* hrq = sh_hr + quarter * 16;
    #pragma unroll
    for (int j = 0; j < 8; j++) {
        float lo, hi;
        asm("mov.b64 {%0, %1}, %2;" : "=f"(lo), "=f"(hi) : "l"(accA[j]));
        partA = fmaf(hrq[2 * j], lo, partA);
        partA = fmaf(hrq[2 * j + 1], hi, partA);
        asm("mov.b64 {%0, %1}, %2;" : "=f"(lo), "=f"(hi) : "l"(accB[j]));
        partB = fmaf(hrq[2 * j], lo, partB);
        partB = fmaf(hrq[2 * j + 1], hi, partB);
    }

    if (quarter != 0) {
        sh_part[(quarter - 1) * WORDS + wA] = partA;
        sh_part[(quarter - 1) * WORDS + wB] = partB;
    }
    __syncthreads();

    double v = 0.0;
    if (quarter == 0) {
        int nA = base + wA;
        if (nA < N) {
            float covf = partA + sh_part[wA] + sh_part[WORDS + wA] + sh_part[2 * WORDS + wA];
            double cov = (double)covf * (double)pAa * (double)pAb;
            float c = coeff[nA];
            v = (double)(c * c) / cov;
        }
        int nB = base + wB;
        if (nB < N) {
            float covf = partB + sh_part[wB] + sh_part[WORDS + wB] + sh_part[2 * WORDS + wB];
            double cov = (double)covf * (double)pBa * (double)pBb;
            float c = coeff[nB];
            v += (double)(c * c) / cov;
        }
        #pragma unroll
        for (int off = 16; off; off >>= 1)
            v += __shfl_down_sync(0xFFFFFFFFu, v, off);
        if (lane == 0) sh_red[group] = v;
    }
    __syncthreads();
    if (tid == 0) {
        double s = 0.0;
        #pragma unroll
        for (int w = 0; w < 4; w++) s += sh_red[w];
        atomicAdd(&g_accum, s);
        __threadfence();
        unsigned int ticket = atomicAdd(&g_count, 1u);
        if (ticket == (unsigned int)(nblocks - 1)) {
            out[0] = (float)g_accum;
        }
    }
}

// ---------------------------------------------------------------------------
extern "C" void kernel_launch(void* const* d_in, const int* in_sizes, int n_in,
                              void* d_out, int out_size) {
    const float* pauli = (const float*)d_in[0];   // [N, 50, 3] f32
    const float* coeff = (const float*)d_in[1];   // [N] f32
    const float* heads = (const float*)d_in[2];   // [64, 50, 3] f32
    const float* hr    = (const float*)d_in[3];   // [64] f32
    const int N = in_sizes[1];

    const size_t smem = (size_t)SMEM_FLOATS * sizeof(float);   // 205632 B
    cudaFuncSetAttribute(main_kernel, cudaFuncAttributeMaxDynamicSharedMemorySize, (int)smem);

    prep_kernel<<<25, 128>>>(heads, hr);
    const int grid = (N + WORDS - 1) / WORDS;
    main_kernel<<<grid, THREADS, smem>>>(pauli, coeff, (float*)d_out, N, grid);
}

// round 10
// speedup vs baseline: 1.2789x; 1.1080x over previous
#include <cuda_runtime.h>
#include <cstdint>

// Problem constants
#define SQ 50
#define SP 3
#define SS 64
#define WORDS 256      // words per block
#define THREADS 256    // 8 warps; 2 quads of 4 warps; thread owns 4 words
#define TROW 158       // padded row stride: 30i mod 32 -> conflict-free LDS.64

// Packed heads: ha[q][j(32)][4] = {h0s0,h0s1,h1s0,h1s1}
//               hcp[q][jp(16)][4] = {h2(2jp)s0,h2(2jp)s1, h2(2jp+1)s0,h2(2jp+1)s1}
#define HA_TOTAL (SQ * 128)   // 6400
#define HCP_TOTAL (SQ * 64)   // 3200

// smem float offsets
#define OFF_HCP  HA_TOTAL               // 6400
#define OFF_HR   (OFF_HCP + HCP_TOTAL)  // 9600
#define OFF_PART (OFF_HR + SS)          // 9664 (3*256 = 768)
#define OFF_RED  (OFF_PART + 3*WORDS)   // 10432 (16 floats = 8 doubles)
#define OFF_T    (OFF_RED + 16)         // 10448 (x4B = 41792, 16B aligned)
#define SMEM_FLOATS (OFF_T + WORDS * TROW)   // 50896 floats = 203584 B

__device__ double       g_accum;
__device__ unsigned int g_count;
__device__ float        g_ha[HA_TOTAL];
__device__ float        g_hcp[HCP_TOTAL];
__device__ float        g_hr[SS];

__device__ __forceinline__ float softplus20(float x) {
    float y = x * 20.0f;
    return fmaxf(y, 0.0f) + log1pf(expf(-fabsf(y)));
}

// ---------------------------------------------------------------------------
__global__ void prep_kernel(const float* __restrict__ heads_param,
                            const float* __restrict__ hr_param) {
    const int tid = threadIdx.x;

    if (blockIdx.x == 0 && tid == 0) { g_accum = 0.0; g_count = 0u; }

    __shared__ float s_hr[SS];
    if (tid < SS) s_hr[tid] = softplus20(hr_param[tid]);
    __syncthreads();
    if (blockIdx.x == 0 && tid < SS) {
        float s = 0.0f;
        #pragma unroll
        for (int i = 0; i < SS; i++) s += s_hr[i];
        s = fmaxf(s, 1e-12f);
        g_hr[tid] = (s_hr[tid] / s + 0.001f / (float)SS) / 1.001f;
    }

    const int stride = blockDim.x * gridDim.x;
    for (int i = blockIdx.x * blockDim.x + tid; i < SS * SQ; i += stride) {
        int s = i / SQ;
        int q = i - s * SQ;
        const float* hp = heads_param + (s * SQ + q) * SP;
        float h0 = softplus20(hp[0]);
        float h1 = softplus20(hp[1]);
        float h2 = softplus20(hp[2]);
        float inv = 1.0f / fmaxf(h0 + h1 + h2, 1e-12f);
        h0 *= inv; h1 *= inv; h2 *= inv;
        int j = s >> 1, o = s & 1;
        int jp = j >> 1, jo = j & 1;
        g_ha[q * 128 + j * 4 + 0 + o]       = h0;
        g_ha[q * 128 + j * 4 + 2 + o]       = h1;
        g_hcp[q * 64 + jp * 4 + jo * 2 + o] = h2;
    }
}

// ---------------------------------------------------------------------------
// Apply one q to 4 words x 8 head-pairs. All-nonneg inner sums.
// ---------------------------------------------------------------------------
__device__ __forceinline__ void proc_q4(
    const ulonglong2* __restrict__ ha,   // + quarter*8, entries j=0..7
    const ulonglong2* __restrict__ hcp,  // + quarter*4, entries jp=0..3
    const uint64_t* __restrict__ R0,     // [4] words, (r0,r0) packs
    const uint64_t* __restrict__ R1,     // [4]
    uint64_t acc[4][8])
{
    #pragma unroll
    for (int jp = 0; jp < 4; jp++) {
        ulonglong2 HcP = hcp[jp];
        ulonglong2 Ha0 = ha[2 * jp];
        ulonglong2 Ha1 = ha[2 * jp + 1];
        #pragma unroll
        for (int k = 0; k < 4; k++) {
            uint64_t d, e;
            asm("fma.rn.f32x2 %0, %1, %2, %3;" : "=l"(d) : "l"(Ha0.x), "l"(R0[k]), "l"(HcP.x));
            asm("fma.rn.f32x2 %0, %1, %2, %3;" : "=l"(d) : "l"(Ha0.y), "l"(R1[k]), "l"(d));
            asm("mul.rn.f32x2 %0, %1, %2;" : "=l"(acc[k][2*jp]) : "l"(acc[k][2*jp]), "l"(d));
            asm("fma.rn.f32x2 %0, %1, %2, %3;" : "=l"(e) : "l"(Ha1.x), "l"(R0[k]), "l"(HcP.y));
            asm("fma.rn.f32x2 %0, %1, %2, %3;" : "=l"(e) : "l"(Ha1.y), "l"(R1[k]), "l"(e));
            asm("mul.rn.f32x2 %0, %1, %2;" : "=l"(acc[k][2*jp+1]) : "l"(acc[k][2*jp+1]), "l"(e));
        }
    }
}

// ---------------------------------------------------------------------------
// Main: quad g = wid>>2 covers words [g*128,(g+1)*128); quarter = wid&3 handles
// head pairs quarter*8..+7. Thread words: lane + 32k, k = 0..3.
// ---------------------------------------------------------------------------
__global__ void __launch_bounds__(THREADS, 1)
main_kernel(const float* __restrict__ pauli,
            const float* __restrict__ coeff,
            float* __restrict__ out,
            int N, int nblocks) {
    extern __shared__ float smem[];
    float*  sh_ha   = smem;
    float*  sh_hcp  = smem + OFF_HCP;
    float*  sh_hr   = smem + OFF_HR;
    float*  sh_part = smem + OFF_PART;
    double* sh_red  = (double*)(smem + OFF_RED);
    float*  sh_t    = smem + OFF_T;

    const int tid  = threadIdx.x;
    const int wid  = tid >> 5;
    const int lane = tid & 31;

    // Stage heads tables
    {
        const float4* src = (const float4*)g_ha;
        float4*       dst = (float4*)sh_ha;
        #pragma unroll
        for (int i = tid; i < HA_TOTAL / 4; i += THREADS) dst[i] = src[i];
        const float4* src2 = (const float4*)g_hcp;
        float4*       dst2 = (float4*)sh_hcp;
        #pragma unroll
        for (int i = tid; i < HCP_TOTAL / 4; i += THREADS) dst2[i] = src2[i];
    }
    if (tid < SS) sh_hr[tid] = g_hr[tid];

    // Stage pauli tile: float2 coalesced reads, padded-row scatter
    const int base  = blockIdx.x * WORDS;
    const int valid = min(WORDS, N - base);
    const float2* gsrc2 = (const float2*)(pauli + (size_t)base * (SQ * SP));
    for (int i = tid; i < valid * 75; i += THREADS) {
        int w = i / 75;
        int k = i - w * 75;
        *(float2*)(sh_t + w * TROW + 2 * k) = gsrc2[i];
    }
    __syncthreads();

    const int quarter = wid & 3;
    const int group   = wid >> 2;
    int w4[4];
    const float* trow[4];
    #pragma unroll
    for (int k = 0; k < 4; k++) {
        w4[k] = group * 128 + lane + 32 * k;
        trow[k] = sh_t + w4[k] * TROW;
    }

    uint64_t acc[4][8];
    #pragma unroll
    for (int k = 0; k < 4; k++)
        #pragma unroll
        for (int j = 0; j < 8; j++) acc[k][j] = 0x3F8000003F800000ull;
    float pa[4] = {1.0f, 1.0f, 1.0f, 1.0f};
    float pb[4] = {1.0f, 1.0f, 1.0f, 1.0f};

    const ulonglong2* ha_base  = (const ulonglong2*)sh_ha  + quarter * 8;
    const ulonglong2* hcp_base = (const ulonglong2*)sh_hcp + quarter * 4;

    #pragma unroll 1
    for (int c = 0; c < 25; c++) {       // chunk of 2 qubits: q0=2c, q1=2c+1
        uint64_t R0a[4], R1a[4], R0b[4], R1b[4];
        #pragma unroll
        for (int k = 0; k < 4; k++) {
            const float2* tp = (const float2*)(trow[k] + 6 * c);
            float2 v0 = tp[0], v1 = tp[1], v2 = tp[2];
            // q0: t=(v0.x, v0.y, v1.x); q1: t=(v1.y, v2.x, v2.y)
            float t2c0 = fmaxf(v1.x, 1e-12f);
            float t2c1 = fmaxf(v2.y, 1e-12f);
            float rc0, rc1;
            asm("rcp.approx.f32 %0, %1;" : "=f"(rc0) : "f"(t2c0));
            asm("rcp.approx.f32 %0, %1;" : "=f"(rc1) : "f"(t2c1));
            float r00 = v0.x * rc0, r10 = v0.y * rc0;
            float r01 = v1.y * rc1, r11 = v2.x * rc1;
            if (c <= 12) pa[k] *= t2c0; else pb[k] *= t2c0;
            if (c <= 11) pa[k] *= t2c1; else pb[k] *= t2c1;
            asm("mov.b64 %0, {%1, %1};" : "=l"(R0a[k]) : "f"(r00));
            asm("mov.b64 %0, {%1, %1};" : "=l"(R1a[k]) : "f"(r10));
            asm("mov.b64 %0, {%1, %1};" : "=l"(R0b[k]) : "f"(r01));
            asm("mov.b64 %0, {%1, %1};" : "=l"(R1b[k]) : "f"(r11));
        }
        proc_q4(ha_base + (2*c)     * 32, hcp_base + (2*c)     * 16, R0a, R1a, acc);
        proc_q4(ha_base + (2*c + 1) * 32, hcp_base + (2*c + 1) * 16, R0b, R1b, acc);
    }

    // hr-weighted sums over this quarter's 16 heads, per word
    float part[4];
    const float* hrq = sh_hr + quarter * 16;
    #pragma unroll
    for (int k = 0; k < 4; k++) {
        float p = 0.0f;
        #pragma unroll
        for (int j = 0; j < 8; j++) {
            float lo, hi;
            asm("mov.b64 {%0, %1}, %2;" : "=f"(lo), "=f"(hi) : "l"(acc[k][j]));
            p = fmaf(hrq[2 * j], lo, p);
            p = fmaf(hrq[2 * j + 1], hi, p);
        }
        part[k] = p;
    }

    if (quarter != 0) {
        #pragma unroll
        for (int k = 0; k < 4; k++)
            sh_part[(quarter - 1) * WORDS + w4[k]] = part[k];
    }
    __syncthreads();

    double v = 0.0;
    if (quarter == 0) {
        #pragma unroll
        for (int k = 0; k < 4; k++) {
            int n = base + w4[k];
            if (n < N) {
                float covf = part[k] + sh_part[w4[k]]
                           + sh_part[WORDS + w4[k]] + sh_part[2 * WORDS + w4[k]];
                double cov = (double)covf * (double)pa[k] * (double)pb[k];
                float c = coeff[n];
                v += (double)(c * c) / cov;
            }
        }
        #pragma unroll
        for (int off = 16; off; off >>= 1)
            v += __shfl_down_sync(0xFFFFFFFFu, v, off);
        if (lane == 0) sh_red[group] = v;
    }
    __syncthreads();
    if (tid == 0) {
        double s = sh_red[0] + sh_red[1];
        atomicAdd(&g_accum, s);
        __threadfence();
        unsigned int ticket = atomicAdd(&g_count, 1u);
        if (ticket == (unsigned int)(nblocks - 1)) {
            out[0] = (float)g_accum;
        }
    }
}

// ---------------------------------------------------------------------------
extern "C" void kernel_launch(void* const* d_in, const int* in_sizes, int n_in,
                              void* d_out, int out_size) {
    const float* pauli = (const float*)d_in[0];   // [N, 50, 3] f32
    const float* coeff = (const float*)d_in[1];   // [N] f32
    const float* heads = (const float*)d_in[2];   // [64, 50, 3] f32
    const float* hr    = (const float*)d_in[3];   // [64] f32
    const int N = in_sizes[1];

    const size_t smem = (size_t)SMEM_FLOATS * sizeof(float);   // 203584 B
    cudaFuncSetAttribute(main_kernel, cudaFuncAttributeMaxDynamicSharedMemorySize, (int)smem);

    prep_kernel<<<25, 128>>>(heads, hr);
    const int grid = (N + WORDS - 1) / WORDS;
    main_kernel<<<grid, THREADS, smem>>>(pauli, coeff, (float*)d_out, N, grid);
}